// round 8
// baseline (speedup 1.0000x reference)
#include <cuda_runtime.h>
#include <cstdint>

// StableMoEGate via 3xTF32 mma.sync (m16n8k8), K-split 2.
// x pre-split at stage time; fragment-interleaved smem; LDS.64 frag loads.
// out (f32): [scores 2T][idx-as-float 2T][aux 1]

#define T_TOKENS 16384
#define H_DIM    4096
#define E_EXP    64
#define BM       128
#define KC       32
#define KHALF    (H_DIM / 2)     // 2048
#define NCH      (KHALF / KC)    // 64 chunks per CTA
#define RSW      72              // row stride words: [big 32][sml 32][pad 8]; 72%32==8 -> conflict-free frags
#define XBYTES   (BM * RSW * 4)          // 36864
#define WBYTES   (E_EXP * RSW * 4)       // 18432
#define BUFBYTES (XBYTES + WBYTES)       // 55296
#define SMEMSZ   (2 * BUFBYTES)          // 110592

__device__ float g_W2[128 * E_EXP * 64];           // 2 MB: [chunk 128][e 64][big32|sml32] interleaved
__device__ float g_part0[T_TOKENS * E_EXP];        // 4 MB partial (K half 0)
__device__ float g_part1[T_TOKENS * E_EXP];        // 4 MB partial (K half 1)

__device__ __forceinline__ uint32_t tf32_bits(float a) {
    uint32_t r; asm("cvt.rna.tf32.f32 %0, %1;" : "=r"(r) : "f"(a));
    return r;
}
__device__ __forceinline__ void cp16(uint32_t smem, const void* gmem) {
    asm volatile("cp.async.cg.shared.global [%0], [%1], 16;" :: "r"(smem), "l"(gmem));
}
__device__ __forceinline__ void lds64(uint32_t addr, uint32_t& r0, uint32_t& r1) {
    asm volatile("ld.shared.v2.b32 {%0,%1}, [%2];" : "=r"(r0), "=r"(r1) : "r"(addr));
}
__device__ __forceinline__ void sts128(uint32_t addr, float a, float b, float c, float d) {
    asm volatile("st.shared.v4.b32 [%0], {%1,%2,%3,%4};"
                 :: "r"(addr), "f"(a), "f"(b), "f"(c), "f"(d) : "memory");
}
__device__ __forceinline__ void mma8(float* d, uint32_t a0, uint32_t a1, uint32_t a2, uint32_t a3,
                                     uint32_t b0, uint32_t b1) {
    asm volatile(
        "mma.sync.aligned.m16n8k8.row.col.f32.tf32.tf32.f32 "
        "{%0,%1,%2,%3}, {%4,%5,%6,%7}, {%8,%9}, {%0,%1,%2,%3};"
        : "+f"(d[0]), "+f"(d[1]), "+f"(d[2]), "+f"(d[3])
        : "r"(a0), "r"(a1), "r"(a2), "r"(a3), "r"(b0), "r"(b1));
}

// ---------------- W split + interleave pre-kernel ----------------
// g_W2[s][e][j]: j in [0,32) = big part interleaved, [32,64) = small part.
// Interleave within each k8 block: pos(kk) = (kk&3)*2 + (kk>>2).
__global__ void wsplit(const float* __restrict__ W) {
    int i = blockIdx.x * blockDim.x + threadIdx.x;
    if (i < E_EXP * H_DIM) {
        int e = i >> 12, k = i & 4095;
        int s = k >> 5, kl = k & 31;
        int blk = kl >> 3, kk = kl & 7;
        int pos = (kk & 3) * 2 + (kk >> 2);
        float w = W[(size_t)e * H_DIM + k];
        float b = __uint_as_float(tf32_bits(w));
        size_t base = ((size_t)s * E_EXP + e) * 64 + blk * 8 + pos;
        g_W2[base]      = b;
        g_W2[base + 32] = w - b;   // consumed as tf32 (residual ~2^-23)
    }
}

// ---------------- GEMM kernel: one CTA = 128 tokens x 64 experts x K-half ----
__global__ void __launch_bounds__(256, 2)
gate_gemm(const float* __restrict__ x) {
    extern __shared__ __align__(16) char dsm[];
    const uint32_t base = (uint32_t)__cvta_generic_to_shared(dsm);

    const int tid  = threadIdx.x;
    const int warp = tid >> 5, lane = tid & 31;
    const int grp  = lane >> 2, tig = lane & 3;
    const int wm   = warp & 3;            // token  group *32
    const int wn   = warp >> 2;           // expert group *32
    const int tile = blockIdx.x >> 1;
    const int kh   = blockIdx.x & 1;
    const int tb   = tile * BM;
    const int sgl  = kh * NCH;            // global chunk offset for this K half
    float* gpart   = kh ? g_part1 : g_part0;

    const int xrow  = tid >> 1;           // staging: row, 2 threads per row
    const int xhalf = tid & 1;            // 16 floats each

    float acc[2][4][4];
#pragma unroll
    for (int mt = 0; mt < 2; ++mt)
#pragma unroll
        for (int nt = 0; nt < 4; ++nt)
#pragma unroll
            for (int i = 0; i < 4; ++i) acc[mt][nt][i] = 0.0f;

    // ---- helpers ----
    auto cpW = [&](int s, int buf) {      // 1024 x 16B from g_W2 chunk (sgl+s)
        const float* src = g_W2 + ((size_t)(sgl + s) * E_EXP) * 64;
        uint32_t dst = base + buf * BUFBYTES + XBYTES;
#pragma unroll
        for (int r = 0; r < 4; ++r) {
            int id = tid + 256 * r;
            int e = id >> 4, seg = id & 15;
            cp16(dst + e * (RSW * 4) + seg * 16, src + (size_t)e * 64 + seg * 4);
        }
        asm volatile("cp.async.commit_group;" ::: "memory");
    };
    auto ldgX = [&](int s, float4* v) {
        const float* src = x + (size_t)(tb + xrow) * H_DIM + (sgl + s) * KC + xhalf * 16;
        v[0] = *reinterpret_cast<const float4*>(src + 0);
        v[1] = *reinterpret_cast<const float4*>(src + 4);
        v[2] = *reinterpret_cast<const float4*>(src + 8);
        v[3] = *reinterpret_cast<const float4*>(src + 12);
    };
    auto stsX = [&](int buf, const float4* v) {
        const float* f = reinterpret_cast<const float*>(v);   // 16 consecutive k values
        float big[16], sml[16];
#pragma unroll
        for (int i = 0; i < 16; ++i) {
            big[i] = __uint_as_float(tf32_bits(f[i]));
            sml[i] = f[i] - big[i];
        }
        uint32_t wb = base + buf * BUFBYTES + (xrow * RSW + xhalf * 16) * 4;
        // pos order per k8 block: words [0..3] = k{0,4,1,5}, [4..7] = k{2,6,3,7}
        sts128(wb + 0,   big[0],  big[4],  big[1],  big[5]);
        sts128(wb + 16,  big[2],  big[6],  big[3],  big[7]);
        sts128(wb + 32,  big[8],  big[12], big[9],  big[13]);
        sts128(wb + 48,  big[10], big[14], big[11], big[15]);
        uint32_t ws = wb + 32 * 4;
        sts128(ws + 0,   sml[0],  sml[4],  sml[1],  sml[5]);
        sts128(ws + 16,  sml[2],  sml[6],  sml[3],  sml[7]);
        sts128(ws + 32,  sml[8],  sml[12], sml[9],  sml[13]);
        sts128(ws + 48,  sml[10], sml[14], sml[11], sml[15]);
    };

    // ---- prologue: stage chunk 0 ----
    float4 v[4];
    ldgX(0, v);
    cpW(0, 0);
    stsX(0, v);

    for (int s = 0; s < NCH; ++s) {
        const int b = s & 1;
        asm volatile("cp.async.wait_group 0;" ::: "memory");
        __syncthreads();
        if (s + 1 < NCH) {
            cpW(s + 1, b ^ 1);
            ldgX(s + 1, v);
        }

        // ---- compute chunk s from buf b ----
        const uint32_t xa = base + b * BUFBYTES + ((32 * wm + grp) * RSW + tig * 2) * 4;
        const uint32_t wa = base + b * BUFBYTES + XBYTES + ((8 * wn * 4 + grp) * RSW + tig * 2) * 4;
        // note: wn*32 experts handled as 4 nt-blocks of 8 rows below
#pragma unroll
        for (int ks = 0; ks < 4; ++ks) {
            const uint32_t ko = ks * 8 * 4;     // 8 words per k8 block
            uint32_t ab[2][4], as[2][4];        // [mt]{a0,a1,a2,a3}
#pragma unroll
            for (int mt = 0; mt < 2; ++mt) {
                uint32_t r0 = xa + mt * (16 * RSW * 4) + ko;
                lds64(r0,                 ab[mt][0], ab[mt][2]);
                lds64(r0 + 8 * RSW * 4,   ab[mt][1], ab[mt][3]);
                lds64(r0 + 128,               as[mt][0], as[mt][2]);   // +32 words
                lds64(r0 + 8 * RSW * 4 + 128, as[mt][1], as[mt][3]);
            }
            uint32_t bb[4][2], bs[4][2];
#pragma unroll
            for (int nt = 0; nt < 4; ++nt) {
                uint32_t r0 = wa + nt * (8 * RSW * 4) + ko;
                lds64(r0,       bb[nt][0], bb[nt][1]);
                lds64(r0 + 128, bs[nt][0], bs[nt][1]);
            }
            // pass-major: 8 independent MMAs between accumulator reuses
#pragma unroll
            for (int mt = 0; mt < 2; ++mt)
#pragma unroll
                for (int nt = 0; nt < 4; ++nt)
                    mma8(acc[mt][nt], ab[mt][0], ab[mt][1], ab[mt][2], ab[mt][3], bb[nt][0], bb[nt][1]);
#pragma unroll
            for (int mt = 0; mt < 2; ++mt)
#pragma unroll
                for (int nt = 0; nt < 4; ++nt)
                    mma8(acc[mt][nt], ab[mt][0], ab[mt][1], ab[mt][2], ab[mt][3], bs[nt][0], bs[nt][1]);
#pragma unroll
            for (int mt = 0; mt < 2; ++mt)
#pragma unroll
                for (int nt = 0; nt < 4; ++nt)
                    mma8(acc[mt][nt], as[mt][0], as[mt][1], as[mt][2], as[mt][3], bb[nt][0], bb[nt][1]);
        }

        if (s + 1 < NCH) stsX(b ^ 1, v);
    }

    // ---- write partial logits [token][expert] ----
#pragma unroll
    for (int mt = 0; mt < 2; ++mt)
#pragma unroll
        for (int nt = 0; nt < 4; ++nt) {
            int r0 = tb + wm * 32 + mt * 16 + grp;
            int c0 = wn * 32 + nt * 8 + tig * 2;
            *reinterpret_cast<float2*>(&gpart[(size_t)r0 * E_EXP + c0]) =
                make_float2(acc[mt][nt][0], acc[mt][nt][1]);
            *reinterpret_cast<float2*>(&gpart[(size_t)(r0 + 8) * E_EXP + c0]) =
                make_float2(acc[mt][nt][2], acc[mt][nt][3]);
        }
}

// ---------------- combine + top-2 kernel: warp per token ----------------
__global__ void __launch_bounds__(256)
gate_combine(float* __restrict__ out, int out_size) {
    const int lane = threadIdx.x & 31;
    const int warp = threadIdx.x >> 5;
    const int t = blockIdx.x * 8 + warp;

    const float2* p0 = reinterpret_cast<const float2*>(g_part0 + (size_t)t * E_EXP);
    const float2* p1 = reinterpret_cast<const float2*>(g_part1 + (size_t)t * E_EXP);
    float2 a = p0[lane], b = p1[lane];
    const float e0 = a.x + b.x;
    const float e1 = a.y + b.y;
    const int j0 = 2 * lane, j1 = 2 * lane + 1;

    float v1, v2; int i1, i2;
    if (e0 >= e1) { v1 = e0; i1 = j0; v2 = e1; i2 = j1; }
    else          { v1 = e1; i1 = j1; v2 = e0; i2 = j0; }

#pragma unroll
    for (int off = 16; off > 0; off >>= 1) {
        float ov1 = __shfl_xor_sync(0xffffffffu, v1, off);
        int   oi1 = __shfl_xor_sync(0xffffffffu, i1, off);
        float ov2 = __shfl_xor_sync(0xffffffffu, v2, off);
        int   oi2 = __shfl_xor_sync(0xffffffffu, i2, off);
        if (ov1 > v1 || (ov1 == v1 && oi1 < i1)) {
            v2 = v1; i2 = i1; v1 = ov1; i1 = oi1;
            if (ov2 > v2 || (ov2 == v2 && oi2 < i2)) { v2 = ov2; i2 = oi2; }
        } else {
            if (ov1 > v2 || (ov1 == v2 && oi1 < i2))      { v2 = ov1; i2 = oi1; }
            else if (ov2 > v2 || (ov2 == v2 && oi2 < i2)) { v2 = ov2; i2 = oi2; }
        }
    }

    const float m = v1;
    float ssum = expf(e0 - m) + expf(e1 - m);
#pragma unroll
    for (int off = 16; off > 0; off >>= 1)
        ssum += __shfl_xor_sync(0xffffffffu, ssum, off);

    if (lane == 0) {
        const float invZ = 1.0f / ssum;
        const float s1 = invZ;                    // exp(v1-m)=1
        const float s2 = expf(v2 - m) * invZ;
        const float r  = expf(s2 - s1);           // renorm softmax (max = s1)
        const float o1 = 1.0f / (1.0f + r);
        const float o2 = r * o1;
        out[2 * t]     = o1;
        out[2 * t + 1] = o2;
        out[2 * T_TOKENS + 2 * t]     = (float)i1;
        out[2 * T_TOKENS + 2 * t + 1] = (float)i2;
    }
    if (blockIdx.x == 0) {
        for (int i = 4 * T_TOKENS + (int)threadIdx.x; i < out_size; i += 256)
            out[i] = 0.0f;
    }
}

extern "C" void kernel_launch(void* const* d_in, const int* in_sizes, int n_in,
                              void* d_out, int out_size) {
    const float* x;
    const float* W;
    if (in_sizes[0] == E_EXP * H_DIM && in_sizes[1] != E_EXP * H_DIM) {
        W = (const float*)d_in[0];
        x = (const float*)d_in[1];
    } else {
        x = (const float*)d_in[0];
        W = (const float*)d_in[1];
    }
    float* out = (float*)d_out;

    cudaFuncSetAttribute(gate_gemm, cudaFuncAttributeMaxDynamicSharedMemorySize, SMEMSZ);

    wsplit<<<(E_EXP * H_DIM + 255) / 256, 256>>>(W);
    gate_gemm<<<(T_TOKENS / BM) * 2, 256, SMEMSZ>>>(x);
    gate_combine<<<T_TOKENS / 8, 256>>>(out, out_size);
}